// round 17
// baseline (speedup 1.0000x reference)
#include <cuda_runtime.h>
#include <cuda_fp16.h>
#include <cstdint>
#include <math_constants.h>

// ---------------------------------------------------------------------------
// Device scratch (static: allocation-free)
// ---------------------------------------------------------------------------
__device__ __half g_a [65536 * 256];   // A pixel-major [m][c] = fp16(x)
__device__ __half g_bh[512 * 256];     // normalized proto fp16 [p][c]
__device__ float  g_pnf[512 * 256];    // normalized protos fp32 (for fixup)
__device__ int4   g_fixdata[65536];    // {m, i1, i2, bits(v3)}
__device__ int    g_nfix;
__device__ int    g_fblist[65536];     // fallback pixels (verification failed)
__device__ int    g_nfb;

__device__ __forceinline__ uint32_t smem_u32(const void* p) {
    uint32_t a;
    asm("{ .reg .u64 t; cvta.to.shared.u64 t, %1; cvt.u32.u64 %0, t; }"
        : "=r"(a) : "l"(p));
    return a;
}
__device__ __forceinline__ void cpa16(uint32_t dst, const void* src) {
    asm volatile("cp.async.cg.shared.global [%0], [%1], 16;"
                 :: "r"(dst), "l"(src));
}
#define LDSM_X4(r0,r1,r2,r3,addr) \
    asm volatile("ldmatrix.sync.aligned.m8n8.x4.shared.b16 {%0,%1,%2,%3}, [%4];" \
        : "=r"(r0),"=r"(r1),"=r"(r2),"=r"(r3) : "r"(addr))
#define MMA16816(d,a,b) \
    asm volatile("mma.sync.aligned.m16n8k16.row.col.f32.f16.f16.f32 " \
        "{%0,%1,%2,%3},{%4,%5,%6,%7},{%8,%9},{%0,%1,%2,%3};" \
        : "+f"(d[0]),"+f"(d[1]),"+f"(d[2]),"+f"(d[3]) \
        : "r"(a[0]),"r"(a[1]),"r"(a[2]),"r"(a[3]),"r"(b[0]),"r"(b[1]))

// fp16-GEMM absolute error std ~3.2e-4; flag threshold 2.5e-3 = ~8 sigma,
// verification margin 3e-3 = ~9 sigma.
#define FIX_THRESH 2.5e-3f
#define E_VER      3e-3f

// ---------------------------------------------------------------------------
// Prep 1: normalize protos -> fp16 + fp32 copies; reset counters
// ---------------------------------------------------------------------------
__global__ void proto_prep_kernel(const float* __restrict__ proto) {
    __shared__ float sred[8];
    const int p = blockIdx.x, c = threadIdx.x;
    float v = proto[(p << 8) + c];
    float ss = v * v;
    #pragma unroll
    for (int s = 16; s >= 1; s >>= 1) ss += __shfl_xor_sync(0xffffffffu, ss, s);
    if ((c & 31) == 0) sred[c >> 5] = ss;
    __syncthreads();
    float tot = 0.f;
    #pragma unroll
    for (int w = 0; w < 8; ++w) tot += sred[w];
    const float pn = v / fmaxf(sqrtf(tot), 1e-12f);
    g_pnf[(p << 8) + c] = pn;
    g_bh[(p << 8) + c] = __float2half(pn);
    if (p == 0 && c == 0) { g_nfix = 0; g_nfb = 0; }
}

// ---------------------------------------------------------------------------
// Prep 2: transpose x [b][c][m] -> A [m][c] fp16, half2 stores.
// ---------------------------------------------------------------------------
__global__ void xsplit_kernel(const float* __restrict__ x) {
    __shared__ float t[32][66];
    const int b = blockIdx.z, c0 = blockIdx.x << 6, m0 = blockIdx.y << 5;
    const int lane = threadIdx.x & 31, w = threadIdx.x >> 5;
    #pragma unroll
    for (int i = 0; i < 8; ++i) {
        int c = w + (i << 3);
        t[lane][c] = x[b * 262144 + (c0 + c) * 1024 + m0 + lane];
    }
    __syncthreads();
    __half2* ga2 = reinterpret_cast<__half2*>(g_a);
    #pragma unroll
    for (int j = 0; j < 4; ++j) {
        int m = w + (j << 3);
        float2 f = *reinterpret_cast<const float2*>(&t[m][lane << 1]);
        __half2 h = __halves2half2(__float2half(f.x), __float2half(f.y));
        ga2[((size_t)(b * 1024 + m0 + m) << 7) + (c0 >> 1) + lane] = h;
    }
}

// ---------------------------------------------------------------------------
// B slice loader (256 threads): 128 protos x 64 ch fp16 = 16KB into buf (t%3).
// ---------------------------------------------------------------------------
__device__ __forceinline__ void load_bslice(uint32_t Bsm, int t, int tid) {
    const int pc = t >> 2, kb = t & 3;
    const char* src0 = reinterpret_cast<const char*>(g_bh);
    const uint32_t dst = Bsm + (uint32_t)(t % 3) * 16384u;
    #pragma unroll
    for (int i = 0; i < 4; ++i) {
        int u = tid + (i << 8);          // 0..1023 16B units
        int r = u >> 3, c = u & 7;
        uint32_t o = (uint32_t)(r << 7) + (uint32_t)(c << 4);
        const char* src = src0 + (size_t)(pc * 128 + r) * 512 + kb * 128 + (c << 4);
        cpa16(dst + (o ^ ((o >> 3) & 0x70)), src);
    }
}

// ---------------------------------------------------------------------------
// Main: 512 blocks x 128 pixels, 256 threads (8 warps, 4m x 2n grid,
// 32x64 tile/warp). A (128x256 fp16, 64KB) staged once; 16 B slices
// 3-stage pipelined. fp16 GEMM, fp32 acc, TOP-3 + fused gather epilogue.
// ---------------------------------------------------------------------------
__global__ __launch_bounds__(256)
void protomatch_mma(const float* __restrict__ proto,
                    float* __restrict__ out, long long out_size)
{
    extern __shared__ char dsm[];
    const uint32_t dynb = smem_u32(dsm);
    const uint32_t base = (dynb + 1023u) & ~1023u;
    char* base_g = dsm + (base - dynb);
    const uint32_t Asm = base;            // 65536 bytes (4 chunks x 16KB)
    const uint32_t Bsm = base + 65536u;   // 49152 bytes (3 bufs x 16KB)

    const int tid = threadIdx.x, lane = tid & 31, wid = tid >> 5;
    const int warp_m = wid & 3, warp_n = wid >> 2;   // 4 x 2
    const int m0 = blockIdx.x << 7;      // 128 pixels per block
    const int b = m0 >> 10, n0 = m0 & 1023;

    // ---- stage A (128 rows x 256 fp16 = 64KB) + first two B slices ----
    const char* Ag = reinterpret_cast<const char*>(g_a);
    #pragma unroll
    for (int i = 0; i < 16; ++i) {
        int u = tid + (i << 8);          // 0..4095 16B units
        int s = u >> 10;                 // chunk 0..3
        int r = (u >> 3) & 127;          // row 0..127
        int c = u & 7;                   // 16B col 0..7
        uint32_t o = (uint32_t)(r << 7) + (uint32_t)(c << 4);
        cpa16(Asm + (s << 14) + (o ^ ((o >> 3) & 0x70)),
              Ag + (size_t)(m0 + r) * 512 + (s << 7) + (c << 4));
    }
    load_bslice(Bsm, 0, tid);
    asm volatile("cp.async.commit_group;");
    load_bslice(Bsm, 1, tid);
    asm volatile("cp.async.commit_group;");

    // per-lane ldmatrix address components
    uint32_t aoff[2], aswz[2];
    #pragma unroll
    for (int mt = 0; mt < 2; ++mt) {
        int rowA = warp_m * 32 + mt * 16 + (lane & 15);
        aoff[mt] = (uint32_t)rowA << 7;
        aswz[mt] = (uint32_t)(rowA & 7);
    }
    const uint32_t alc = (uint32_t)(lane >> 4);

    uint32_t boff[4], bswz[4];
    #pragma unroll
    for (int nt2 = 0; nt2 < 4; ++nt2) {
        int rowB = warp_n * 64 + nt2 * 16 + ((lane >> 4) << 3) + (lane & 7);
        boff[nt2] = (uint32_t)rowB << 7;
        bswz[nt2] = (uint32_t)(rowB & 7);
    }
    const uint32_t blc = (uint32_t)((lane >> 3) & 1);

    float acc[2][8][4];
    float t1v[4], t2v[4], t3v[4];
    int   t1i[4], t2i[4], t3i[4];
    #pragma unroll
    for (int s = 0; s < 4; ++s) {
        t1v[s] = -CUDART_INF_F; t2v[s] = -CUDART_INF_F; t3v[s] = -CUDART_INF_F;
        t1i[s] = 0; t2i[s] = 0; t3i[s] = 0;
    }

    for (int t = 0; t < 16; ++t) {
        const int pc = t >> 2, kb = t & 3;
        if (kb == 0) {
            #pragma unroll
            for (int i = 0; i < 2; ++i)
                #pragma unroll
                for (int j = 0; j < 8; ++j)
                    #pragma unroll
                    for (int q = 0; q < 4; ++q) acc[i][j][q] = 0.f;
        }
        if (t < 15) asm volatile("cp.async.wait_group 1;");
        else        asm volatile("cp.async.wait_group 0;");
        __syncthreads();
        if (t + 2 < 16) {
            load_bslice(Bsm, t + 2, tid);
            asm volatile("cp.async.commit_group;");
        }

        const uint32_t Ab = Asm + ((uint32_t)kb << 14);
        const uint32_t Bb = Bsm + (uint32_t)(t % 3) * 16384u;

        #pragma unroll
        for (int k16 = 0; k16 < 4; ++k16) {
            uint32_t ra[2][4];
            #pragma unroll
            for (int mt = 0; mt < 2; ++mt) {
                uint32_t c16 = (uint32_t)(k16 << 1) + alc;
                LDSM_X4(ra[mt][0], ra[mt][1], ra[mt][2], ra[mt][3],
                        Ab + aoff[mt] + ((c16 ^ aswz[mt]) << 4));
            }
            #pragma unroll
            for (int nt2 = 0; nt2 < 4; ++nt2) {
                uint32_t c16 = (uint32_t)(k16 << 1) + blc;
                uint32_t rb[4];
                LDSM_X4(rb[0], rb[1], rb[2], rb[3],
                        Bb + boff[nt2] + ((c16 ^ bswz[nt2]) << 4));
                MMA16816(acc[0][2*nt2+0], ra[0], (rb + 0));
                MMA16816(acc[1][2*nt2+0], ra[1], (rb + 0));
                MMA16816(acc[0][2*nt2+1], ra[0], (rb + 2));
                MMA16816(acc[1][2*nt2+1], ra[1], (rb + 2));
            }
        }

        if (kb == 3) {     // fold chunk pc into running top-3 (cols ascending)
            #pragma unroll
            for (int mt = 0; mt < 2; ++mt)
                #pragma unroll
                for (int rh = 0; rh < 2; ++rh) {
                    int sl = mt * 2 + rh;
                    #pragma unroll
                    for (int nt = 0; nt < 8; ++nt)
                        #pragma unroll
                        for (int e = 0; e < 2; ++e) {
                            float v = acc[mt][nt][rh * 2 + e];
                            int col = (pc << 7) + (warp_n << 6) + (nt << 3)
                                    + ((lane & 3) << 1) + e;
                            if (v > t1v[sl]) {
                                t3v[sl] = t2v[sl]; t3i[sl] = t2i[sl];
                                t2v[sl] = t1v[sl]; t2i[sl] = t1i[sl];
                                t1v[sl] = v; t1i[sl] = col;
                            } else if (v > t2v[sl]) {
                                t3v[sl] = t2v[sl]; t3i[sl] = t2i[sl];
                                t2v[sl] = v; t2i[sl] = col;
                            } else if (v > t3v[sl]) {
                                t3v[sl] = v; t3i[sl] = col;
                            }
                        }
                }
        }
    }
    __syncthreads();

    // ---- cross-lane/warp reduction via smem (reuse A region) ----
    float* sv1 = reinterpret_cast<float*>(base_g);            // [128][8]
    int*   si1 = reinterpret_cast<int*>(base_g + 4096);
    float* sv2 = reinterpret_cast<float*>(base_g + 8192);
    int*   si2 = reinterpret_cast<int*>(base_g + 12288);
    float* sv3 = reinterpret_cast<float*>(base_g + 16384);
    int*   si3 = reinterpret_cast<int*>(base_g + 20480);
    int*   sIdx = reinterpret_cast<int*>(base_g + 24576);     // [128]
    #pragma unroll
    for (int mt = 0; mt < 2; ++mt)
        #pragma unroll
        for (int rh = 0; rh < 2; ++rh) {
            int sl = mt * 2 + rh;
            int row = warp_m * 32 + mt * 16 + rh * 8 + (lane >> 2);
            int cand = (warp_n << 2) + (lane & 3);
            sv1[row * 8 + cand] = t1v[sl];  si1[row * 8 + cand] = t1i[sl];
            sv2[row * 8 + cand] = t2v[sl];  si2[row * 8 + cand] = t2i[sl];
            sv3[row * 8 + cand] = t3v[sl];  si3[row * 8 + cand] = t3i[sl];
        }
    __syncthreads();

    if (tid < 128) {
        float V1 = -CUDART_INF_F, V2 = -CUDART_INF_F, V3 = -CUDART_INF_F;
        int I1 = 0x7fffffff, I2 = 0x7fffffff, I3 = 0x7fffffff;
        #pragma unroll
        for (int c = 0; c < 8; ++c) {
            #pragma unroll
            for (int k = 0; k < 3; ++k) {
                float v; int i;
                if (k == 0)      { v = sv1[tid * 8 + c]; i = si1[tid * 8 + c]; }
                else if (k == 1) { v = sv2[tid * 8 + c]; i = si2[tid * 8 + c]; }
                else             { v = sv3[tid * 8 + c]; i = si3[tid * 8 + c]; }
                if (v > V1 || (v == V1 && i < I1)) {
                    V3 = V2; I3 = I2; V2 = V1; I2 = I1; V1 = v; I1 = i;
                } else if (v > V2 || (v == V2 && i < I2)) {
                    V3 = V2; I3 = I2; V2 = v; I2 = i;
                } else if (v > V3 || (v == V3 && i < I3)) {
                    V3 = v; I3 = i;
                }
            }
        }
        const int m = m0 + tid;
        sIdx[tid] = I1;
        if (out_size > 16777216LL) out[16777216 + m] = (float)I1;
        if (V1 - V2 < FIX_THRESH) {
            int pos = atomicAdd(&g_nfix, 1);
            g_fixdata[pos] = make_int4(m, I1, I2, __float_as_int(V3));
        }
    }
    __syncthreads();

    // ---- fused gather: recon[b,c,h,w] = proto[idx][c], coalesced ----
    const int n4 = tid & 31;
    const int ph = tid >> 5;
    const float* r0 = proto + (sIdx[(n4 << 2) + 0] << 8);
    const float* r1 = proto + (sIdx[(n4 << 2) + 1] << 8);
    const float* r2 = proto + (sIdx[(n4 << 2) + 2] << 8);
    const float* r3 = proto + (sIdx[(n4 << 2) + 3] << 8);
    float4* Og = reinterpret_cast<float4*>(out) + (b * 65536 + (n0 >> 2) + n4);
    #pragma unroll 4
    for (int c = ph; c < 256; c += 8)
        Og[c * 256] = make_float4(r0[c], r1[c], r2[c], r3[c]);
}

// ---------------------------------------------------------------------------
// fixup_fast: one warp per flagged pixel. Exact fp32 dots for the TWO
// candidates only; verified against v3 + E_VER. Failures -> fallback list.
// ---------------------------------------------------------------------------
__global__ __launch_bounds__(256)
void fixup_fast(const float* __restrict__ x, const float* __restrict__ proto,
                float* __restrict__ out, long long out_size)
{
    const int lane = threadIdx.x & 31, w = threadIdx.x >> 5;
    const int nfix = g_nfix;

    for (int e = blockIdx.x * 8 + w; e < nfix; e += gridDim.x * 8) {
        const int4 fd = g_fixdata[e];
        const int m = fd.x, i1 = fd.y, i2 = fd.z;
        const float v3 = __int_as_float(fd.w);
        const int bb = m >> 10, mi = m & 1023;

        const float* p1 = g_pnf + (i1 << 8);
        const float* p2 = g_pnf + (i2 << 8);
        float d1 = 0.f, d2 = 0.f;
        #pragma unroll
        for (int i = 0; i < 8; ++i) {
            int c = lane + (i << 5);
            float xv = x[bb * 262144 + c * 1024 + mi];
            d1 = fmaf(xv, p1[c], d1);
            d2 = fmaf(xv, p2[c], d2);
        }
        #pragma unroll
        for (int s = 16; s >= 1; s >>= 1) {
            d1 += __shfl_xor_sync(0xffffffffu, d1, s);
            d2 += __shfl_xor_sync(0xffffffffu, d2, s);
        }

        // winner among candidates (tie -> lower proto index)
        int   wi = (d2 > d1 || (d2 == d1 && i2 < i1)) ? i2 : i1;
        float wv = fmaxf(d1, d2);
        int ok = (wv > v3 + E_VER) ? 1 : 0;

        if (!ok) {
            if (lane == 0) {
                int pos = atomicAdd(&g_nfb, 1);
                g_fblist[pos] = m;
            }
            continue;
        }
        if (lane == 0 && out_size > 16777216LL) out[16777216 + m] = (float)wi;
        // patch recon row
        const float* pw = proto + (wi << 8);
        #pragma unroll
        for (int i = 0; i < 8; ++i) {
            int c = lane + (i << 5);
            out[bb * 262144 + c * 1024 + mi] = pw[c];
        }
    }
}

// ---------------------------------------------------------------------------
// fixup_full: full 512-proto exact argmax for fallback pixels (very few).
// 512 threads, one proto per thread, 8 entries/block.
// ---------------------------------------------------------------------------
__global__ __launch_bounds__(512)
void fixup_full(const float* __restrict__ x, const float* __restrict__ proto,
                float* __restrict__ out, long long out_size)
{
    __shared__ __align__(16) float xs[8][260];
    __shared__ float rbv[8][16];
    __shared__ int   rbi[8][16];
    __shared__ int   sfi[8];
    const int tid = threadIdx.x, lane = tid & 31, wid = tid >> 5;
    const int nfb = g_nfb;

    for (int g0 = blockIdx.x * 8; g0 < nfb; g0 += gridDim.x * 8) {
        const int ne = min(8, nfb - g0);
        for (int i = tid; i < (ne << 8); i += 512) {
            int e = i >> 8, c = i & 255;
            int m = g_fblist[g0 + e];
            xs[e][c] = x[(m >> 10) * 262144 + c * 1024 + (m & 1023)];
        }
        __syncthreads();

        const float4* pr = reinterpret_cast<const float4*>(g_pnf + (tid << 8));
        float acc[8];
        #pragma unroll
        for (int e = 0; e < 8; ++e) acc[e] = 0.f;
        #pragma unroll 4
        for (int c4 = 0; c4 < 64; ++c4) {
            float4 pv = pr[c4];
            #pragma unroll
            for (int e = 0; e < 8; ++e) {
                float4 xv = reinterpret_cast<const float4*>(xs[e])[c4];
                acc[e] = fmaf(pv.x, xv.x, acc[e]);
                acc[e] = fmaf(pv.y, xv.y, acc[e]);
                acc[e] = fmaf(pv.z, xv.z, acc[e]);
                acc[e] = fmaf(pv.w, xv.w, acc[e]);
            }
        }

        #pragma unroll
        for (int e = 0; e < 8; ++e) {
            float v = acc[e]; int ix = tid;
            #pragma unroll
            for (int s = 16; s >= 1; s >>= 1) {
                float ov = __shfl_xor_sync(0xffffffffu, v, s);
                int   oi = __shfl_xor_sync(0xffffffffu, ix, s);
                if (ov > v || (ov == v && oi < ix)) { v = ov; ix = oi; }
            }
            if (lane == 0) { rbv[e][wid] = v; rbi[e][wid] = ix; }
        }
        __syncthreads();

        if (tid < ne) {
            float fv = rbv[tid][0]; int fi = rbi[tid][0];
            #pragma unroll
            for (int w = 1; w < 16; ++w)
                if (rbv[tid][w] > fv || (rbv[tid][w] == fv && rbi[tid][w] < fi)) {
                    fv = rbv[tid][w]; fi = rbi[tid][w];
                }
            sfi[tid] = fi;
            const int m = g_fblist[g0 + tid];
            if (out_size > 16777216LL) out[16777216 + m] = (float)fi;
        }
        __syncthreads();

        const int c  = tid & 255;
        const int eh = tid >> 8;
        for (int e = eh; e < ne; e += 2) {
            const int m = g_fblist[g0 + e];
            out[(m >> 10) * 262144 + c * 1024 + (m & 1023)] = proto[(sfi[e] << 8) + c];
        }
        __syncthreads();
    }
}

// ---------------------------------------------------------------------------
extern "C" void kernel_launch(void* const* d_in, const int* in_sizes, int n_in,
                              void* d_out, int out_size)
{
    const float* x     = (const float*)d_in[0];
    const float* proto = (const float*)d_in[1];
    if (n_in >= 2 && in_sizes[0] == 512 * 256 && in_sizes[1] != 512 * 256) {
        proto = (const float*)d_in[0];
        x     = (const float*)d_in[1];
    }
    float* out = (float*)d_out;

    proto_prep_kernel<<<512, 256>>>(proto);
    xsplit_kernel<<<dim3(4, 32, 64), 256>>>(x);

    cudaFuncSetAttribute(protomatch_mma,
                         cudaFuncAttributeMaxDynamicSharedMemorySize, 115712);
    protomatch_mma<<<512, 256, 115712>>>(proto, out, (long long)out_size);

    fixup_fast<<<128, 256>>>(x, proto, out, (long long)out_size);
    fixup_full<<<16, 512>>>(x, proto, out, (long long)out_size);
}